// round 1
// baseline (speedup 1.0000x reference)
#include <cuda_runtime.h>
#include <cuda_bf16.h>
#include <cstdint>

#define N_NODES   100000
#define N_EDGES   600000
#define D_FEAT    128
#define N_CLASSES 64
#define NOUT      128          // 64 (P) + 64 (Q) fused outputs per node

// Scratch: per-node projections. PQ[n][0:64] = h[n]@Wu^T + b ; PQ[n][64:128] = h[n]@Wv^T
__device__ float g_PQ[(size_t)N_NODES * NOUT];
// Transposed fused weight: g_Wt[k*128 + j] = V[j][k], V[j] = Wu[j] (j<64) else Wv[j-64]
__device__ float g_Wt[128 * 128];

// ---------------------------------------------------------------------------
// Kernel 0: transpose/fuse W (64x256 row-major) into g_Wt (k-major). One-time, tiny.
// ---------------------------------------------------------------------------
__global__ void transpose_w_kernel(const float* __restrict__ W) {
    int idx = blockIdx.x * blockDim.x + threadIdx.x;   // 0..16383
    if (idx >= 128 * 128) return;
    int k = idx >> 7;          // 0..127
    int j = idx & 127;         // 0..127
    float v;
    if (j < 64) v = W[j * 256 + k];            // Wu[j][k]
    else        v = W[(j - 64) * 256 + 128 + k]; // Wv[j-64][k]
    g_Wt[k * 128 + j] = v;
}

// ---------------------------------------------------------------------------
// Kernel 1: GEMM  PQ[n][j] = sum_k h[n][k] * V[j][k]  (+ b[j] for j<64)
// Block tile: 128 nodes x 128 outputs, K=128 fully in smem.
// 256 threads, each computes 8 nodes x 8 cols using packed f32x2 FMAs.
// ---------------------------------------------------------------------------
__global__ void __launch_bounds__(256, 1)
gemm_kernel(const float* __restrict__ h, const float* __restrict__ b) {
    extern __shared__ float smem[];
    float* Ws = smem;                 // [128][128]  k-major: Ws[k*128 + j]
    float* Hs = smem + 128 * 128;     // [128][129]  node-major padded: Hs[row*129 + k]

    const int tid   = threadIdx.x;
    const int node0 = blockIdx.x * 128;

    // Load transposed weights, fully coalesced (L2-hot after first wave)
    {
        const float4* src = (const float4*)g_Wt;
        float4* dst = (float4*)Ws;
        #pragma unroll
        for (int i = tid; i < 128 * 32; i += 256) dst[i] = src[i];
    }
    // Load h tile (coalesced float4 reads, scalar smem stores into padded rows)
    #pragma unroll
    for (int i = tid; i < 128 * 32; i += 256) {
        int row = i >> 5;
        int c4  = i & 31;
        int gr  = node0 + row;
        if (gr >= N_NODES) gr = N_NODES - 1;   // clamp; stores are guarded later
        float4 v = *(const float4*)&h[(size_t)gr * D_FEAT + c4 * 4];
        float* d = &Hs[row * 129 + c4 * 4];
        d[0] = v.x; d[1] = v.y; d[2] = v.z; d[3] = v.w;
    }
    __syncthreads();

    const int r = tid >> 4;   // 0..15 : node sub-tile
    const int q = tid & 15;   // 0..15 : col  sub-tile
    const float* hsBase = &Hs[(r * 8) * 129];

    unsigned long long acc[8][4];
    #pragma unroll
    for (int x = 0; x < 8; ++x)
        #pragma unroll
        for (int j = 0; j < 4; ++j) acc[x][j] = 0ull;   // packed {0.f, 0.f}

    #pragma unroll 4
    for (int k = 0; k < 128; ++k) {
        // a: 8 broadcast scalar LDS (2 distinct addrs/warp, different banks via pad 129)
        unsigned long long aa[8];
        #pragma unroll
        for (int x = 0; x < 8; ++x) {
            float av = hsBase[x * 129 + k];
            asm("mov.b64 %0, {%1, %1};" : "=l"(aa[x]) : "f"(av));
        }
        // b: 8 consecutive cols = 2x 16B vector LDS, reinterpreted as packed f32x2
        const float* wrow = &Ws[k * 128 + q * 8];
        ulonglong2 v0 = *(const ulonglong2*)wrow;
        ulonglong2 v1 = *(const ulonglong2*)(wrow + 4);
        unsigned long long bb[4] = { v0.x, v0.y, v1.x, v1.y };

        #pragma unroll
        for (int x = 0; x < 8; ++x)
            #pragma unroll
            for (int j = 0; j < 4; ++j)
                asm("fma.rn.f32x2 %0, %1, %2, %0;"
                    : "+l"(acc[x][j]) : "l"(aa[x]), "l"(bb[j]));
    }

    // Epilogue: unpack, add bias (only output cols < 64 carry b), store float4s
    float bias[8];
    #pragma unroll
    for (int i = 0; i < 8; ++i)
        bias[i] = (q < 8) ? b[q * 8 + i] : 0.0f;

    #pragma unroll
    for (int x = 0; x < 8; ++x) {
        int node = node0 + r * 8 + x;
        if (node < N_NODES) {
            float v[8];
            #pragma unroll
            for (int j = 0; j < 4; ++j)
                asm("mov.b64 {%0, %1}, %2;" : "=f"(v[2 * j]), "=f"(v[2 * j + 1]) : "l"(acc[x][j]));
            #pragma unroll
            for (int i = 0; i < 8; ++i) v[i] += bias[i];
            float4* o = (float4*)&g_PQ[(size_t)node * NOUT + q * 8];
            o[0] = make_float4(v[0], v[1], v[2], v[3]);
            o[1] = make_float4(v[4], v[5], v[6], v[7]);
        }
    }
}

// ---------------------------------------------------------------------------
// Kernel 2: gather-add.  out[e][c] = PQ[src[e]][c] + PQ[dst[e]][64+c]
// One thread per (edge, float4-chunk): 16 chunks cover 64 output cols.
// ---------------------------------------------------------------------------
__global__ void __launch_bounds__(256)
gather_kernel(const int* __restrict__ src, const int* __restrict__ dst,
              float* __restrict__ out) {
    int t = blockIdx.x * blockDim.x + threadIdx.x;
    if (t >= N_EDGES * 16) return;
    int e = t >> 4;
    int q = t & 15;

    unsigned int s = (unsigned int)__ldg(&src[e]);
    unsigned int d = (unsigned int)__ldg(&dst[e]);
    if (s >= N_NODES) s = 0;   // clamp (defensive; also catches dtype surprises without UB)
    if (d >= N_NODES) d = 0;

    float4 p = *(const float4*)&g_PQ[(size_t)s * NOUT + q * 4];
    float4 r = *(const float4*)&g_PQ[(size_t)d * NOUT + 64 + q * 4];
    float4 o = make_float4(p.x + r.x, p.y + r.y, p.z + r.z, p.w + r.w);
    ((float4*)out)[(size_t)e * 16 + q] = o;
}

// ---------------------------------------------------------------------------
extern "C" void kernel_launch(void* const* d_in, const int* in_sizes, int n_in,
                              void* d_out, int out_size) {
    const float* h   = (const float*)d_in[0];
    const int*   src = (const int*)  d_in[1];   // jnp "int64" -> int32 under default JAX x64=off
    const int*   dst = (const int*)  d_in[2];
    const float* W   = (const float*)d_in[3];
    const float* b   = (const float*)d_in[4];
    float* out = (float*)d_out;

    const int smem_bytes = (128 * 128 + 128 * 129) * sizeof(float);  // 131,584 B
    cudaFuncSetAttribute(gemm_kernel, cudaFuncAttributeMaxDynamicSharedMemorySize, smem_bytes);

    transpose_w_kernel<<<64, 256>>>(W);

    const int nblk = (N_NODES + 127) / 128;   // 782
    gemm_kernel<<<nblk, 256, smem_bytes>>>(h, b);

    const int gthreads = N_EDGES * 16;        // 9.6M
    gather_kernel<<<(gthreads + 255) / 256, 256>>>(src, dst, out);
}

// round 3
// speedup vs baseline: 1.5233x; 1.5233x over previous
#include <cuda_runtime.h>
#include <cuda_bf16.h>
#include <cstdint>

#define N_NODES   100000
#define N_EDGES   600000
#define D_FEAT    128
#define NOUT      128          // 64 (P = h@Wu^T + b) + 64 (Q = h@Wv^T)

// ---------------------------------------------------------------------------
// Device scratch
// ---------------------------------------------------------------------------
__device__ float g_PQ[(size_t)N_NODES * NOUT];
// Pre-split fused weight [j=0..127][k=0..127] bf16, in the GEMM's swizzled smem
// image (256B rows, 16B-chunk xor swizzle) so blocks can copy it linearly.
__device__ __align__(16) unsigned char g_Bhi[128 * 256];
__device__ __align__(16) unsigned char g_Blo[128 * 256];
__device__ float g_bias[128];   // b for cols 0..63, zeros for 64..127

// Swizzled byte offset inside a [row][k] bf16 tile with 256B row stride:
// 16B chunks within the row are xor-permuted by (row & 7).
__device__ __forceinline__ uint32_t tswz(int row, int kbyte) {
    return (uint32_t)(row * 256 + (kbyte ^ ((row & 7) << 4)));
}

__device__ __forceinline__ uint32_t smem_u32(const void* p) {
    uint32_t a;
    asm("{ .reg .u64 t; cvta.to.shared.u64 t, %1; cvt.u32.u64 %0, t; }" : "=r"(a) : "l"(p));
    return a;
}

__device__ __forceinline__ void ldsm_x4(uint32_t addr, uint32_t* r) {
    asm volatile("ldmatrix.sync.aligned.m8n8.x4.shared.b16 {%0,%1,%2,%3}, [%4];"
                 : "=r"(r[0]), "=r"(r[1]), "=r"(r[2]), "=r"(r[3]) : "r"(addr));
}
__device__ __forceinline__ void ldsm_x2(uint32_t addr, uint32_t* r) {
    asm volatile("ldmatrix.sync.aligned.m8n8.x2.shared.b16 {%0,%1}, [%2];"
                 : "=r"(r[0]), "=r"(r[1]) : "r"(addr));
}
__device__ __forceinline__ void mma_bf16(float* c, const uint32_t* a, const uint32_t* b) {
    asm volatile("mma.sync.aligned.m16n8k16.row.col.f32.bf16.bf16.f32 "
                 "{%0,%1,%2,%3}, {%4,%5,%6,%7}, {%8,%9}, {%0,%1,%2,%3};"
                 : "+f"(c[0]), "+f"(c[1]), "+f"(c[2]), "+f"(c[3])
                 : "r"(a[0]), "r"(a[1]), "r"(a[2]), "r"(a[3]), "r"(b[0]), "r"(b[1]));
}

// ---------------------------------------------------------------------------
// Kernel 0: prep — split W to bf16 hi/lo into the swizzled B image + bias
// ---------------------------------------------------------------------------
__global__ void prep_kernel(const float* __restrict__ W, const float* __restrict__ b) {
    int idx = blockIdx.x * blockDim.x + threadIdx.x;   // 0..16383
    if (idx < 128) g_bias[idx] = (idx < 64) ? b[idx] : 0.0f;
    if (idx >= 128 * 128) return;
    int j = idx >> 7;     // output col (N dim), 0..127
    int k = idx & 127;    // K dim
    float v = (j < 64) ? W[j * 256 + k] : W[(j - 64) * 256 + 128 + k];
    __nv_bfloat16 hi = __float2bfloat16_rn(v);
    float lo = v - __bfloat162float(hi);
    __nv_bfloat16 lob = __float2bfloat16_rn(lo);
    uint32_t off = tswz(j, k * 2);
    *(__nv_bfloat16*)(g_Bhi + off) = hi;
    *(__nv_bfloat16*)(g_Blo + off) = lob;
}

// ---------------------------------------------------------------------------
// Kernel 1: HMMA GEMM.  PQ[node0+m][j] = sum_k h[m][k]*V[j][k] + bias[j]
// bf16x3 split, fp32 accumulate. 128x128 tile, 8 warps (2 x 4), 64x32 each.
// ---------------------------------------------------------------------------
#define SM_AHI   0
#define SM_ALO   32768
#define SM_BHI   65536
#define SM_BLO   98304
#define SM_BIAS  131072
#define SM_TOTAL 131584

__global__ void __launch_bounds__(256, 1)
gemm_kernel(const float* __restrict__ h) {
    extern __shared__ char smem[];
    const uint32_t sm_base = smem_u32(smem);
    const int tid = threadIdx.x;
    const int wid = tid >> 5;
    const int lid = tid & 31;
    const int node0 = blockIdx.x * 128;

    // ---- Stage B: linear layout-preserving copy of pre-split images (2x32KB)
    {
        const float4* shi = (const float4*)g_Bhi;
        const float4* slo = (const float4*)g_Blo;
        float4* dhi = (float4*)(smem + SM_BHI);
        float4* dlo = (float4*)(smem + SM_BLO);
        #pragma unroll
        for (int i = tid; i < 2048; i += 256) { dhi[i] = shi[i]; dlo[i] = slo[i]; }
    }
    if (tid < 128) *(float*)(smem + SM_BIAS + tid * 4) = g_bias[tid];

    // ---- Stage A: load h [128x128] f32, split bf16 hi/lo, swizzled 8B stores
    #pragma unroll
    for (int i = tid; i < 4096; i += 256) {
        int m  = i >> 5;                  // 0..127
        int k4 = i & 31;                  // float4 index along K
        int gm = node0 + m; if (gm >= N_NODES) gm = N_NODES - 1;
        float4 v = *(const float4*)&h[(size_t)gm * D_FEAT + k4 * 4];
        __nv_bfloat162 h0 = __float22bfloat162_rn(make_float2(v.x, v.y));
        __nv_bfloat162 h1 = __float22bfloat162_rn(make_float2(v.z, v.w));
        float2 f0 = __bfloat1622float2(h0);
        float2 f1 = __bfloat1622float2(h1);
        __nv_bfloat162 l0 = __float22bfloat162_rn(make_float2(v.x - f0.x, v.y - f0.y));
        __nv_bfloat162 l1 = __float22bfloat162_rn(make_float2(v.z - f1.x, v.w - f1.y));
        uint32_t off = tswz(m, k4 * 8);
        *(uint2*)(smem + SM_AHI + off) = make_uint2(*(uint32_t*)&h0, *(uint32_t*)&h1);
        *(uint2*)(smem + SM_ALO + off) = make_uint2(*(uint32_t*)&l0, *(uint32_t*)&l1);
    }
    __syncthreads();

    // ---- Mainloop
    const int wm = wid & 1;     // 64-row half
    const int wn = wid >> 1;    // 32-col quarter

    // ldmatrix per-lane geometry
    const int a_row = (lid & 7) + ((lid >> 3) & 1) * 8;  // row within m16 frag
    const int a_kb  = (lid >> 4) * 16;                   // 0 / 16 within 32B k-step
    const int b_row = (lid & 7);                         // row within n8 frag
    const int b_kb  = ((lid >> 3) & 1) * 16;
    const int xora  = (lid & 7) << 4;                    // swizzle xor (row&7 == lid&7)

    float acc[4][4][4];
    #pragma unroll
    for (int mf = 0; mf < 4; ++mf)
        #pragma unroll
        for (int nf = 0; nf < 4; ++nf)
            #pragma unroll
            for (int i = 0; i < 4; ++i) acc[mf][nf][i] = 0.0f;

    #pragma unroll
    for (int ks = 0; ks < 8; ++ks) {
        uint32_t ahi[4][4], alo[4][4], bhi[4][2], blo[4][2];
        const uint32_t akoff = (uint32_t)((ks * 32 + a_kb) ^ xora);
        const uint32_t bkoff = (uint32_t)((ks * 32 + b_kb) ^ xora);
        #pragma unroll
        for (int mf = 0; mf < 4; ++mf) {
            uint32_t ro = (uint32_t)((wm * 64 + mf * 16 + a_row) * 256) + akoff;
            ldsm_x4(sm_base + SM_AHI + ro, ahi[mf]);
            ldsm_x4(sm_base + SM_ALO + ro, alo[mf]);
        }
        #pragma unroll
        for (int nf = 0; nf < 4; ++nf) {
            uint32_t ro = (uint32_t)((wn * 32 + nf * 8 + b_row) * 256) + bkoff;
            ldsm_x2(sm_base + SM_BHI + ro, bhi[nf]);
            ldsm_x2(sm_base + SM_BLO + ro, blo[nf]);
        }
        #pragma unroll
        for (int mf = 0; mf < 4; ++mf)
            #pragma unroll
            for (int nf = 0; nf < 4; ++nf) {
                mma_bf16(acc[mf][nf], ahi[mf], bhi[nf]);
                mma_bf16(acc[mf][nf], ahi[mf], blo[nf]);
                mma_bf16(acc[mf][nf], alo[mf], bhi[nf]);
            }
    }

    // ---- Epilogue: c-frag (row=lid/4, col=(lid%4)*2) + bias -> g_PQ
    const int trow = lid >> 2;
    const int tcol = (lid & 3) * 2;
    #pragma unroll
    for (int mf = 0; mf < 4; ++mf) {
        const int node_a = node0 + wm * 64 + mf * 16 + trow;
        const int node_b = node_a + 8;
        #pragma unroll
        for (int nf = 0; nf < 4; ++nf) {
            const int col = wn * 32 + nf * 8 + tcol;
            float2 bs = *(float2*)(smem + SM_BIAS + col * 4);
            if (node_a < N_NODES) {
                float2 o = make_float2(acc[mf][nf][0] + bs.x, acc[mf][nf][1] + bs.y);
                *(float2*)&g_PQ[(size_t)node_a * NOUT + col] = o;
            }
            if (node_b < N_NODES) {
                float2 o = make_float2(acc[mf][nf][2] + bs.x, acc[mf][nf][3] + bs.y);
                *(float2*)&g_PQ[(size_t)node_b * NOUT + col] = o;
            }
        }
    }
}

// ---------------------------------------------------------------------------
// Kernel 2: gather-add.  out[e][c] = PQ[src[e]][c] + PQ[dst[e]][64+c]
// ---------------------------------------------------------------------------
__global__ void __launch_bounds__(256)
gather_kernel(const int* __restrict__ src, const int* __restrict__ dst,
              float* __restrict__ out) {
    int t = blockIdx.x * blockDim.x + threadIdx.x;
    if (t >= N_EDGES * 16) return;
    int e = t >> 4;
    int q = t & 15;

    unsigned int s = (unsigned int)__ldg(&src[e]);
    unsigned int d = (unsigned int)__ldg(&dst[e]);
    if (s >= N_NODES) s = 0;
    if (d >= N_NODES) d = 0;

    float4 p = *(const float4*)&g_PQ[(size_t)s * NOUT + q * 4];
    float4 r = *(const float4*)&g_PQ[(size_t)d * NOUT + 64 + q * 4];
    float4 o = make_float4(p.x + r.x, p.y + r.y, p.z + r.z, p.w + r.w);
    __stcs((float4*)out + (size_t)e * 16 + q, o);   // streaming: keep L2 for PQ
}

// ---------------------------------------------------------------------------
extern "C" void kernel_launch(void* const* d_in, const int* in_sizes, int n_in,
                              void* d_out, int out_size) {
    const float* h   = (const float*)d_in[0];
    const int*   src = (const int*)  d_in[1];
    const int*   dst = (const int*)  d_in[2];
    const float* W   = (const float*)d_in[3];
    const float* b   = (const float*)d_in[4];
    float* out = (float*)d_out;

    cudaFuncSetAttribute(gemm_kernel, cudaFuncAttributeMaxDynamicSharedMemorySize, SM_TOTAL);

    prep_kernel<<<64, 256>>>(W, b);

    const int nblk = (N_NODES + 127) / 128;   // 782
    gemm_kernel<<<nblk, 256, SM_TOTAL>>>(h);

    const int gthreads = N_EDGES * 16;        // 9.6M
    gather_kernel<<<(gthreads + 255) / 256, 256>>>(src, dst, out);
}

// round 4
// speedup vs baseline: 1.8050x; 1.1850x over previous
#include <cuda_runtime.h>
#include <cuda_bf16.h>
#include <cuda_fp16.h>
#include <cstdint>

#define N_NODES   100000
#define N_EDGES   600000
#define D_FEAT    128
#define NOUT      128          // 64 (P = h@Wu^T + b) + 64 (Q = h@Wv^T)

// ---------------------------------------------------------------------------
// Device scratch: per-node projections in fp16 (halves gather traffic;
// values ~N(0,0.5), far inside fp16 range; adds ~3e-4 RMS rel err).
// ---------------------------------------------------------------------------
__device__ __half g_PQh[(size_t)N_NODES * NOUT];

// Swizzled byte offset inside a [row][k] bf16 tile with 256B row stride:
// 16B chunks within the row are xor-permuted by (row & 7).
__device__ __forceinline__ uint32_t tswz(int row, int kbyte) {
    return (uint32_t)(row * 256 + (kbyte ^ ((row & 7) << 4)));
}

__device__ __forceinline__ uint32_t smem_u32(const void* p) {
    uint32_t a;
    asm("{ .reg .u64 t; cvta.to.shared.u64 t, %1; cvt.u32.u64 %0, t; }" : "=r"(a) : "l"(p));
    return a;
}

__device__ __forceinline__ void ldsm_x4(uint32_t addr, uint32_t* r) {
    asm volatile("ldmatrix.sync.aligned.m8n8.x4.shared.b16 {%0,%1,%2,%3}, [%4];"
                 : "=r"(r[0]), "=r"(r[1]), "=r"(r[2]), "=r"(r[3]) : "r"(addr));
}
__device__ __forceinline__ void ldsm_x2(uint32_t addr, uint32_t* r) {
    asm volatile("ldmatrix.sync.aligned.m8n8.x2.shared.b16 {%0,%1}, [%2];"
                 : "=r"(r[0]), "=r"(r[1]) : "r"(addr));
}
__device__ __forceinline__ void mma_bf16(float* c, const uint32_t* a, const uint32_t* b) {
    asm volatile("mma.sync.aligned.m16n8k16.row.col.f32.bf16.bf16.f32 "
                 "{%0,%1,%2,%3}, {%4,%5,%6,%7}, {%8,%9}, {%0,%1,%2,%3};"
                 : "+f"(c[0]), "+f"(c[1]), "+f"(c[2]), "+f"(c[3])
                 : "r"(a[0]), "r"(a[1]), "r"(a[2]), "r"(a[3]), "r"(b[0]), "r"(b[1]));
}

// Split a float4 into bf16 hi/lo pairs and store 8B each at swizzled offset.
__device__ __forceinline__ void split_store(char* smem, int hi_off, int lo_off,
                                            int row, int k4, float4 v) {
    __nv_bfloat162 h0 = __float22bfloat162_rn(make_float2(v.x, v.y));
    __nv_bfloat162 h1 = __float22bfloat162_rn(make_float2(v.z, v.w));
    float2 f0 = __bfloat1622float2(h0);
    float2 f1 = __bfloat1622float2(h1);
    __nv_bfloat162 l0 = __float22bfloat162_rn(make_float2(v.x - f0.x, v.y - f0.y));
    __nv_bfloat162 l1 = __float22bfloat162_rn(make_float2(v.z - f1.x, v.w - f1.y));
    uint32_t off = tswz(row, k4 * 8);
    *(uint2*)(smem + hi_off + off) = make_uint2(*(uint32_t*)&h0, *(uint32_t*)&h1);
    *(uint2*)(smem + lo_off + off) = make_uint2(*(uint32_t*)&l0, *(uint32_t*)&l1);
}

// ---------------------------------------------------------------------------
// Kernel 1: HMMA GEMM. PQh[node0+m][j] = fp16( sum_k h[m][k]*V[j][k] + bias[j] )
// bf16x3 split (hi*hi + hi*lo + lo*hi), fp32 accumulate.
// 128x128 tile, 8 warps (2 x 4), 64x32 per warp. W split in-block (no prep pass).
// ---------------------------------------------------------------------------
#define SM_AHI   0
#define SM_ALO   32768
#define SM_BHI   65536
#define SM_BLO   98304
#define SM_TOTAL 131072

__global__ void __launch_bounds__(256, 1)
gemm_kernel(const float* __restrict__ h, const float* __restrict__ W,
            const float* __restrict__ b) {
    extern __shared__ char smem[];
    const uint32_t sm_base = smem_u32(smem);
    const int tid = threadIdx.x;
    const int wid = tid >> 5;
    const int lid = tid & 31;
    const int node0 = blockIdx.x * 128;

    // ---- Stage B: read W straight from gmem (L2-hot), split bf16 hi/lo
    #pragma unroll
    for (int i = tid; i < 4096; i += 256) {
        int j  = i >> 5;                  // output col (B row), 0..127
        int k4 = i & 31;
        const float* wp = (j < 64) ? &W[j * 256 + k4 * 4]
                                   : &W[(j - 64) * 256 + 128 + k4 * 4];
        split_store(smem, SM_BHI, SM_BLO, j, k4, *(const float4*)wp);
    }

    // ---- Stage A: load h [128x128] f32, split bf16 hi/lo
    #pragma unroll
    for (int i = tid; i < 4096; i += 256) {
        int m  = i >> 5;                  // 0..127
        int k4 = i & 31;
        int gm = node0 + m; if (gm >= N_NODES) gm = N_NODES - 1;
        float4 v = *(const float4*)&h[(size_t)gm * D_FEAT + k4 * 4];
        split_store(smem, SM_AHI, SM_ALO, m, k4, v);
    }
    __syncthreads();

    // ---- Mainloop
    const int wm = wid & 1;     // 64-row half
    const int wn = wid >> 1;    // 32-col quarter

    const int a_row = (lid & 7) + ((lid >> 3) & 1) * 8;
    const int a_kb  = (lid >> 4) * 16;
    const int b_row = (lid & 7);
    const int b_kb  = ((lid >> 3) & 1) * 16;
    const int xora  = (lid & 7) << 4;

    float acc[4][4][4];
    #pragma unroll
    for (int mf = 0; mf < 4; ++mf)
        #pragma unroll
        for (int nf = 0; nf < 4; ++nf)
            #pragma unroll
            for (int i = 0; i < 4; ++i) acc[mf][nf][i] = 0.0f;

    #pragma unroll
    for (int ks = 0; ks < 8; ++ks) {
        uint32_t ahi[4][4], alo[4][4], bhi[4][2], blo[4][2];
        const uint32_t akoff = (uint32_t)((ks * 32 + a_kb) ^ xora);
        const uint32_t bkoff = (uint32_t)((ks * 32 + b_kb) ^ xora);
        #pragma unroll
        for (int mf = 0; mf < 4; ++mf) {
            uint32_t ro = (uint32_t)((wm * 64 + mf * 16 + a_row) * 256) + akoff;
            ldsm_x4(sm_base + SM_AHI + ro, ahi[mf]);
            ldsm_x4(sm_base + SM_ALO + ro, alo[mf]);
        }
        #pragma unroll
        for (int nf = 0; nf < 4; ++nf) {
            uint32_t ro = (uint32_t)((wn * 32 + nf * 8 + b_row) * 256) + bkoff;
            ldsm_x2(sm_base + SM_BHI + ro, bhi[nf]);
            ldsm_x2(sm_base + SM_BLO + ro, blo[nf]);
        }
        #pragma unroll
        for (int mf = 0; mf < 4; ++mf)
            #pragma unroll
            for (int nf = 0; nf < 4; ++nf) {
                mma_bf16(acc[mf][nf], ahi[mf], bhi[nf]);
                mma_bf16(acc[mf][nf], ahi[mf], blo[nf]);
                mma_bf16(acc[mf][nf], alo[mf], bhi[nf]);
            }
    }

    // ---- Epilogue: add bias (cols<64 only), convert to fp16, store half2
    const int trow = lid >> 2;
    const int tcol = (lid & 3) * 2;
    #pragma unroll
    for (int mf = 0; mf < 4; ++mf) {
        const int node_a = node0 + wm * 64 + mf * 16 + trow;
        const int node_b = node_a + 8;
        #pragma unroll
        for (int nf = 0; nf < 4; ++nf) {
            const int col = wn * 32 + nf * 8 + tcol;
            float2 bs = (col < 64) ? *(const float2*)&b[col] : make_float2(0.f, 0.f);
            if (node_a < N_NODES) {
                __half2 hv = __floats2half2_rn(acc[mf][nf][0] + bs.x,
                                               acc[mf][nf][1] + bs.y);
                *(__half2*)&g_PQh[(size_t)node_a * NOUT + col] = hv;
            }
            if (node_b < N_NODES) {
                __half2 hv = __floats2half2_rn(acc[mf][nf][2] + bs.x,
                                               acc[mf][nf][3] + bs.y);
                *(__half2*)&g_PQh[(size_t)node_b * NOUT + col] = hv;
            }
        }
    }
}

// ---------------------------------------------------------------------------
// Kernel 2: gather-add.  out[e][c] = PQh[src[e]][c] + PQh[dst[e]][64+c]
// 8 threads/edge, 16B fp16 loads, fp32 streaming stores.
// ---------------------------------------------------------------------------
__global__ void __launch_bounds__(256)
gather_kernel(const int* __restrict__ src, const int* __restrict__ dst,
              float* __restrict__ out) {
    int t = blockIdx.x * blockDim.x + threadIdx.x;
    if (t >= N_EDGES * 8) return;
    int e = t >> 3;
    int q = t & 7;           // 8 cols per thread

    unsigned int s = (unsigned int)__ldg(&src[e]);
    unsigned int d = (unsigned int)__ldg(&dst[e]);
    if (s >= N_NODES) s = 0;
    if (d >= N_NODES) d = 0;

    uint4 pv = *(const uint4*)&g_PQh[(size_t)s * NOUT + q * 8];        // 8 halves
    uint4 qv = *(const uint4*)&g_PQh[(size_t)d * NOUT + 64 + q * 8];   // 8 halves

    const __half2* ph = (const __half2*)&pv;
    const __half2* qh = (const __half2*)&qv;
    float o[8];
    #pragma unroll
    for (int i = 0; i < 4; ++i) {
        float2 a = __half22float2(ph[i]);
        float2 c = __half22float2(qh[i]);
        o[i * 2]     = a.x + c.x;
        o[i * 2 + 1] = a.y + c.y;
    }
    float* op = out + (size_t)e * 64 + q * 8;
    __stcs((float4*)op,     make_float4(o[0], o[1], o[2], o[3]));
    __stcs((float4*)op + 1, make_float4(o[4], o[5], o[6], o[7]));
}

// ---------------------------------------------------------------------------
extern "C" void kernel_launch(void* const* d_in, const int* in_sizes, int n_in,
                              void* d_out, int out_size) {
    const float* h   = (const float*)d_in[0];
    const int*   src = (const int*)  d_in[1];
    const int*   dst = (const int*)  d_in[2];
    const float* W   = (const float*)d_in[3];
    const float* b   = (const float*)d_in[4];
    float* out = (float*)d_out;

    cudaFuncSetAttribute(gemm_kernel, cudaFuncAttributeMaxDynamicSharedMemorySize, SM_TOTAL);

    const int nblk = (N_NODES + 127) / 128;   // 782
    gemm_kernel<<<nblk, 256, SM_TOTAL>>>(h, W, b);

    const int gthreads = N_EDGES * 8;         // 4.8M
    gather_kernel<<<(gthreads + 255) / 256, 256>>>(src, dst, out);
}

// round 5
// speedup vs baseline: 1.9431x; 1.0765x over previous
#include <cuda_runtime.h>
#include <cuda_bf16.h>
#include <cuda_fp16.h>
#include <cstdint>

#define N_NODES   100000
#define N_EDGES   600000
#define D_FEAT    128
#define NOUT      128          // 64 (P = h@Wu^T + b) + 64 (Q = h@Wv^T)
#define GRIDX     148
#define TILES     782          // ceil(N_NODES / 128)

// ---------------------------------------------------------------------------
// Device scratch: per-node projections in fp16.
// ---------------------------------------------------------------------------
__device__ __half g_PQh[(size_t)N_NODES * NOUT];

// Swizzled byte offset inside a [row][k] bf16 tile with 256B row stride.
__device__ __forceinline__ uint32_t tswz(int row, int kbyte) {
    return (uint32_t)(row * 256 + (kbyte ^ ((row & 7) << 4)));
}

__device__ __forceinline__ uint32_t smem_u32(const void* p) {
    uint32_t a;
    asm("{ .reg .u64 t; cvta.to.shared.u64 t, %1; cvt.u32.u64 %0, t; }" : "=r"(a) : "l"(p));
    return a;
}

__device__ __forceinline__ void ldsm_x4(uint32_t addr, uint32_t* r) {
    asm volatile("ldmatrix.sync.aligned.m8n8.x4.shared.b16 {%0,%1,%2,%3}, [%4];"
                 : "=r"(r[0]), "=r"(r[1]), "=r"(r[2]), "=r"(r[3]) : "r"(addr));
}
__device__ __forceinline__ void ldsm_x2(uint32_t addr, uint32_t* r) {
    asm volatile("ldmatrix.sync.aligned.m8n8.x2.shared.b16 {%0,%1}, [%2];"
                 : "=r"(r[0]), "=r"(r[1]) : "r"(addr));
}
__device__ __forceinline__ void mma_bf16(float* c, const uint32_t* a, const uint32_t* b) {
    asm volatile("mma.sync.aligned.m16n8k16.row.col.f32.bf16.bf16.f32 "
                 "{%0,%1,%2,%3}, {%4,%5,%6,%7}, {%8,%9}, {%0,%1,%2,%3};"
                 : "+f"(c[0]), "+f"(c[1]), "+f"(c[2]), "+f"(c[3])
                 : "r"(a[0]), "r"(a[1]), "r"(a[2]), "r"(a[3]), "r"(b[0]), "r"(b[1]));
}

// Split a float4 into bf16 hi/lo and store 8B each at swizzled offset.
__device__ __forceinline__ void split_store(char* smem, uint32_t hi_off, uint32_t lo_off,
                                            int row, int k4, float4 v) {
    __nv_bfloat162 h0 = __float22bfloat162_rn(make_float2(v.x, v.y));
    __nv_bfloat162 h1 = __float22bfloat162_rn(make_float2(v.z, v.w));
    float2 f0 = __bfloat1622float2(h0);
    float2 f1 = __bfloat1622float2(h1);
    __nv_bfloat162 l0 = __float22bfloat162_rn(make_float2(v.x - f0.x, v.y - f0.y));
    __nv_bfloat162 l1 = __float22bfloat162_rn(make_float2(v.z - f1.x, v.w - f1.y));
    uint32_t off = tswz(row, k4 * 8);
    *(uint2*)(smem + hi_off + off) = make_uint2(*(uint32_t*)&h0, *(uint32_t*)&h1);
    *(uint2*)(smem + lo_off + off) = make_uint2(*(uint32_t*)&l0, *(uint32_t*)&l1);
}

// ---------------------------------------------------------------------------
// Smem layout: B once, A double-buffered.
// ---------------------------------------------------------------------------
#define SM_BHI   0u
#define SM_BLO   32768u
#define SM_A0    65536u         // AHI @ +0, ALO @ +32768
#define SM_A1    131072u
#define SM_TOTAL 196608

// ---------------------------------------------------------------------------
// Kernel 1: persistent HMMA GEMM. bf16x3 split, fp32 accumulate.
// 148 CTAs, each loops over node tiles; W staged once; A double-buffered with
// register prefetch of the next tile issued before the MMA mainloop.
// ---------------------------------------------------------------------------
__global__ void __launch_bounds__(256, 1)
gemm_kernel(const float* __restrict__ h, const float* __restrict__ W,
            const float* __restrict__ b) {
    extern __shared__ char smem[];
    const uint32_t sm_base = smem_u32(smem);
    const int tid = threadIdx.x;
    const int wid = tid >> 5;
    const int lid = tid & 31;

    // ---- Stage B once: read W from gmem, split bf16 hi/lo
    #pragma unroll
    for (int i = tid; i < 4096; i += 256) {
        int j  = i >> 5;
        int k4 = i & 31;
        const float* wp = (j < 64) ? &W[j * 256 + k4 * 4]
                                   : &W[(j - 64) * 256 + 128 + k4 * 4];
        split_store(smem, SM_BHI, SM_BLO, j, k4, *(const float4*)wp);
    }

    // ---- Stage A for first tile into buf0
    {
        const int node0 = blockIdx.x * 128;
        #pragma unroll
        for (int i = 0; i < 16; ++i) {
            int idx = tid + i * 256;
            int m = idx >> 5, k4 = idx & 31;
            int gm = node0 + m; if (gm >= N_NODES) gm = N_NODES - 1;
            float4 v = *(const float4*)&h[(size_t)gm * D_FEAT + k4 * 4];
            split_store(smem, SM_A0, SM_A0 + 32768u, m, k4, v);
        }
    }
    __syncthreads();

    // ---- Per-thread constants
    const int wm = wid & 1;     // 64-row half
    const int wn = wid >> 1;    // 32-col quarter
    const int a_row = (lid & 7) + ((lid >> 3) & 1) * 8;
    const int a_kb  = (lid >> 4) * 16;
    const int b_row = (lid & 7);
    const int b_kb  = ((lid >> 3) & 1) * 16;
    const int xora  = (lid & 7) << 4;
    const int trow = lid >> 2;
    const int tcol = (lid & 3) * 2;

    // Hoist bias (column set is fixed per thread)
    float2 bias2[4];
    #pragma unroll
    for (int nf = 0; nf < 4; ++nf) {
        int col = wn * 32 + nf * 8 + tcol;
        bias2[nf] = (col < 64) ? *(const float2*)&b[col] : make_float2(0.f, 0.f);
    }

    int pb = 0;
    for (int t = blockIdx.x; t < TILES; t += GRIDX, pb ^= 1) {
        const int tn = t + GRIDX;
        const bool pre = (tn < TILES);

        // Prefetch next tile's h into registers (issued before MMA stream)
        float4 regs[16];
        if (pre) {
            const int node0n = tn * 128;
            #pragma unroll
            for (int i = 0; i < 16; ++i) {
                int idx = tid + i * 256;
                int m = idx >> 5, k4 = idx & 31;
                int gm = node0n + m; if (gm >= N_NODES) gm = N_NODES - 1;
                regs[i] = *(const float4*)&h[(size_t)gm * D_FEAT + k4 * 4];
            }
        }

        // ---- MMA mainloop on buffer pb
        const uint32_t abase = sm_base + (pb ? SM_A1 : SM_A0);
        float acc[4][4][4];
        #pragma unroll
        for (int mf = 0; mf < 4; ++mf)
            #pragma unroll
            for (int nf = 0; nf < 4; ++nf)
                #pragma unroll
                for (int i = 0; i < 4; ++i) acc[mf][nf][i] = 0.0f;

        #pragma unroll
        for (int ks = 0; ks < 8; ++ks) {
            uint32_t ahi[4][4], alo[4][4], bhi[4][2], blo[4][2];
            const uint32_t akoff = (uint32_t)((ks * 32 + a_kb) ^ xora);
            const uint32_t bkoff = (uint32_t)((ks * 32 + b_kb) ^ xora);
            #pragma unroll
            for (int mf = 0; mf < 4; ++mf) {
                uint32_t ro = (uint32_t)((wm * 64 + mf * 16 + a_row) * 256) + akoff;
                ldsm_x4(abase + ro, ahi[mf]);
                ldsm_x4(abase + 32768u + ro, alo[mf]);
            }
            #pragma unroll
            for (int nf = 0; nf < 4; ++nf) {
                uint32_t ro = (uint32_t)((wn * 32 + nf * 8 + b_row) * 256) + bkoff;
                ldsm_x2(sm_base + SM_BHI + ro, bhi[nf]);
                ldsm_x2(sm_base + SM_BLO + ro, blo[nf]);
            }
            #pragma unroll
            for (int mf = 0; mf < 4; ++mf)
                #pragma unroll
                for (int nf = 0; nf < 4; ++nf) {
                    mma_bf16(acc[mf][nf], ahi[mf], bhi[nf]);
                    mma_bf16(acc[mf][nf], ahi[mf], blo[nf]);
                    mma_bf16(acc[mf][nf], alo[mf], bhi[nf]);
                }
        }

        // ---- Convert + store prefetched tile into the other buffer
        if (pre) {
            char* obuf = smem + (pb ? SM_A0 : SM_A1);
            #pragma unroll
            for (int i = 0; i < 16; ++i) {
                int idx = tid + i * 256;
                int m = idx >> 5, k4 = idx & 31;
                split_store(obuf, 0u, 32768u, m, k4, regs[i]);
            }
        }

        // ---- Epilogue: bias + fp16 store
        const int node0 = t * 128;
        #pragma unroll
        for (int mf = 0; mf < 4; ++mf) {
            const int node_a = node0 + wm * 64 + mf * 16 + trow;
            const int node_b = node_a + 8;
            #pragma unroll
            for (int nf = 0; nf < 4; ++nf) {
                const int col = wn * 32 + nf * 8 + tcol;
                if (node_a < N_NODES) {
                    __half2 hv = __floats2half2_rn(acc[mf][nf][0] + bias2[nf].x,
                                                   acc[mf][nf][1] + bias2[nf].y);
                    *(__half2*)&g_PQh[(size_t)node_a * NOUT + col] = hv;
                }
                if (node_b < N_NODES) {
                    __half2 hv = __floats2half2_rn(acc[mf][nf][2] + bias2[nf].x,
                                                   acc[mf][nf][3] + bias2[nf].y);
                    *(__half2*)&g_PQh[(size_t)node_b * NOUT + col] = hv;
                }
            }
        }
        __syncthreads();
    }
}

// ---------------------------------------------------------------------------
// Kernel 2: gather-add, 2 edges per thread (4 independent PQ loads in flight).
// out[e][c] = PQh[src[e]][c] + PQh[dst[e]][64+c]
// ---------------------------------------------------------------------------
__global__ void __launch_bounds__(256)
gather_kernel(const int* __restrict__ src, const int* __restrict__ dst,
              float* __restrict__ out) {
    int t = blockIdx.x * blockDim.x + threadIdx.x;
    if (t >= (N_EDGES / 2) * 8) return;
    const int ep = t >> 3;           // edge pair index
    const int q  = t & 7;            // 8-col chunk
    const int e0 = ep * 2;
    const int e1 = e0 + 1;

    unsigned int s0 = (unsigned int)__ldg(&src[e0]);
    unsigned int d0 = (unsigned int)__ldg(&dst[e0]);
    unsigned int s1 = (unsigned int)__ldg(&src[e1]);
    unsigned int d1 = (unsigned int)__ldg(&dst[e1]);
    if (s0 >= N_NODES) s0 = 0;
    if (d0 >= N_NODES) d0 = 0;
    if (s1 >= N_NODES) s1 = 0;
    if (d1 >= N_NODES) d1 = 0;

    uint4 p0 = *(const uint4*)&g_PQh[(size_t)s0 * NOUT + q * 8];
    uint4 r0 = *(const uint4*)&g_PQh[(size_t)d0 * NOUT + 64 + q * 8];
    uint4 p1 = *(const uint4*)&g_PQh[(size_t)s1 * NOUT + q * 8];
    uint4 r1 = *(const uint4*)&g_PQh[(size_t)d1 * NOUT + 64 + q * 8];

    float o0[8], o1[8];
    {
        const __half2* ph = (const __half2*)&p0;
        const __half2* qh = (const __half2*)&r0;
        #pragma unroll
        for (int i = 0; i < 4; ++i) {
            float2 a = __half22float2(ph[i]);
            float2 c = __half22float2(qh[i]);
            o0[i * 2] = a.x + c.x; o0[i * 2 + 1] = a.y + c.y;
        }
    }
    {
        const __half2* ph = (const __half2*)&p1;
        const __half2* qh = (const __half2*)&r1;
        #pragma unroll
        for (int i = 0; i < 4; ++i) {
            float2 a = __half22float2(ph[i]);
            float2 c = __half22float2(qh[i]);
            o1[i * 2] = a.x + c.x; o1[i * 2 + 1] = a.y + c.y;
        }
    }

    float* op0 = out + (size_t)e0 * 64 + q * 8;
    float* op1 = out + (size_t)e1 * 64 + q * 8;
    __stcs((float4*)op0,     make_float4(o0[0], o0[1], o0[2], o0[3]));
    __stcs((float4*)op0 + 1, make_float4(o0[4], o0[5], o0[6], o0[7]));
    __stcs((float4*)op1,     make_float4(o1[0], o1[1], o1[2], o1[3]));
    __stcs((float4*)op1 + 1, make_float4(o1[4], o1[5], o1[6], o1[7]));
}

// ---------------------------------------------------------------------------
extern "C" void kernel_launch(void* const* d_in, const int* in_sizes, int n_in,
                              void* d_out, int out_size) {
    const float* h   = (const float*)d_in[0];
    const int*   src = (const int*)  d_in[1];
    const int*   dst = (const int*)  d_in[2];
    const float* W   = (const float*)d_in[3];
    const float* b   = (const float*)d_in[4];
    float* out = (float*)d_out;

    cudaFuncSetAttribute(gemm_kernel, cudaFuncAttributeMaxDynamicSharedMemorySize, SM_TOTAL);

    gemm_kernel<<<GRIDX, 256, SM_TOTAL>>>(h, W, b);

    const int gthreads = (N_EDGES / 2) * 8;   // 2.4M
    gather_kernel<<<(gthreads + 255) / 256, 256>>>(src, dst, out);
}

// round 6
// speedup vs baseline: 2.4346x; 1.2530x over previous
#include <cuda_runtime.h>
#include <cuda_fp16.h>
#include <cstdint>

#define N_NODES   100000
#define N_EDGES   600000
#define D_FEAT    128
#define NOUT      128          // 64 (P = h@Wu^T + b) + 64 (Q = h@Wv^T)
#define GRIDX     148
#define TILES     782          // ceil(N_NODES / 128)

// ---------------------------------------------------------------------------
// Device scratch: per-node projections in fp16.
// ---------------------------------------------------------------------------
__device__ __half g_PQh[(size_t)N_NODES * NOUT];

// Swizzled byte offset inside a [row][k] fp16 tile with 256B row stride.
__device__ __forceinline__ uint32_t tswz(int row, int kbyte) {
    return (uint32_t)(row * 256 + (kbyte ^ ((row & 7) << 4)));
}

__device__ __forceinline__ uint32_t smem_u32(const void* p) {
    uint32_t a;
    asm("{ .reg .u64 t; cvta.to.shared.u64 t, %1; cvt.u32.u64 %0, t; }" : "=r"(a) : "l"(p));
    return a;
}

__device__ __forceinline__ void ldsm_x4(uint32_t addr, uint32_t* r) {
    asm volatile("ldmatrix.sync.aligned.m8n8.x4.shared.b16 {%0,%1,%2,%3}, [%4];"
                 : "=r"(r[0]), "=r"(r[1]), "=r"(r[2]), "=r"(r[3]) : "r"(addr));
}
__device__ __forceinline__ void ldsm_x2(uint32_t addr, uint32_t* r) {
    asm volatile("ldmatrix.sync.aligned.m8n8.x2.shared.b16 {%0,%1}, [%2];"
                 : "=r"(r[0]), "=r"(r[1]) : "r"(addr));
}
__device__ __forceinline__ void mma_f16(float* c, const uint32_t* a, const uint32_t* b) {
    asm volatile("mma.sync.aligned.m16n8k16.row.col.f32.f16.f16.f32 "
                 "{%0,%1,%2,%3}, {%4,%5,%6,%7}, {%8,%9}, {%0,%1,%2,%3};"
                 : "+f"(c[0]), "+f"(c[1]), "+f"(c[2]), "+f"(c[3])
                 : "r"(a[0]), "r"(a[1]), "r"(a[2]), "r"(a[3]), "r"(b[0]), "r"(b[1]));
}

// Convert float4 -> 2x half2 and store 8B at swizzled offset.
__device__ __forceinline__ void f16_store(char* smem, uint32_t base,
                                          int row, int k4, float4 v) {
    __half2 h0 = __floats2half2_rn(v.x, v.y);
    __half2 h1 = __floats2half2_rn(v.z, v.w);
    uint32_t off = tswz(row, k4 * 8);
    *(uint2*)(smem + base + off) = make_uint2(*(uint32_t*)&h0, *(uint32_t*)&h1);
}

// ---------------------------------------------------------------------------
// Smem layout: B once (fp16), A double-buffered (fp16).
// ---------------------------------------------------------------------------
#define SM_B     0u
#define SM_A0    32768u
#define SM_A1    65536u
#define SM_TOTAL 98304

// ---------------------------------------------------------------------------
// Kernel 1: persistent HMMA GEMM, single-pass fp16, fp32 accumulate.
// 148 CTAs; W staged once; A double-buffered with register prefetch.
// ---------------------------------------------------------------------------
__global__ void __launch_bounds__(256, 1)
gemm_kernel(const float* __restrict__ h, const float* __restrict__ W,
            const float* __restrict__ b) {
    extern __shared__ char smem[];
    const uint32_t sm_base = smem_u32(smem);
    const int tid = threadIdx.x;
    const int wid = tid >> 5;
    const int lid = tid & 31;

    // ---- Stage B once: read W from gmem, convert to fp16
    #pragma unroll
    for (int i = tid; i < 4096; i += 256) {
        int j  = i >> 5;
        int k4 = i & 31;
        const float* wp = (j < 64) ? &W[j * 256 + k4 * 4]
                                   : &W[(j - 64) * 256 + 128 + k4 * 4];
        f16_store(smem, SM_B, j, k4, *(const float4*)wp);
    }

    // ---- Stage A for first tile into buf0
    {
        const int node0 = blockIdx.x * 128;
        #pragma unroll
        for (int i = 0; i < 16; ++i) {
            int idx = tid + i * 256;
            int m = idx >> 5, k4 = idx & 31;
            int gm = node0 + m; if (gm >= N_NODES) gm = N_NODES - 1;
            float4 v = *(const float4*)&h[(size_t)gm * D_FEAT + k4 * 4];
            f16_store(smem, SM_A0, m, k4, v);
        }
    }
    __syncthreads();

    // ---- Per-thread constants
    const int wm = wid & 1;     // 64-row half
    const int wn = wid >> 1;    // 32-col quarter
    const int a_row = (lid & 7) + ((lid >> 3) & 1) * 8;
    const int a_kb  = (lid >> 4) * 16;
    const int b_row = (lid & 7);
    const int b_kb  = ((lid >> 3) & 1) * 16;
    const int xora  = (lid & 7) << 4;
    const int trow = lid >> 2;
    const int tcol = (lid & 3) * 2;

    // Hoist bias (column set fixed per thread)
    float2 bias2[4];
    #pragma unroll
    for (int nf = 0; nf < 4; ++nf) {
        int col = wn * 32 + nf * 8 + tcol;
        bias2[nf] = (col < 64) ? *(const float2*)&b[col] : make_float2(0.f, 0.f);
    }

    int pb = 0;
    for (int t = blockIdx.x; t < TILES; t += GRIDX, pb ^= 1) {
        const int tn = t + GRIDX;
        const bool pre = (tn < TILES);

        // Prefetch next tile's h into registers
        float4 regs[16];
        if (pre) {
            const int node0n = tn * 128;
            #pragma unroll
            for (int i = 0; i < 16; ++i) {
                int idx = tid + i * 256;
                int m = idx >> 5, k4 = idx & 31;
                int gm = node0n + m; if (gm >= N_NODES) gm = N_NODES - 1;
                regs[i] = *(const float4*)&h[(size_t)gm * D_FEAT + k4 * 4];
            }
        }

        // ---- MMA mainloop (single fp16 pass)
        const uint32_t abase = sm_base + (pb ? SM_A1 : SM_A0);
        float acc[4][4][4];
        #pragma unroll
        for (int mf = 0; mf < 4; ++mf)
            #pragma unroll
            for (int nf = 0; nf < 4; ++nf)
                #pragma unroll
                for (int i = 0; i < 4; ++i) acc[mf][nf][i] = 0.0f;

        #pragma unroll
        for (int ks = 0; ks < 8; ++ks) {
            uint32_t af[4][4], bf[4][2];
            const uint32_t akoff = (uint32_t)((ks * 32 + a_kb) ^ xora);
            const uint32_t bkoff = (uint32_t)((ks * 32 + b_kb) ^ xora);
            #pragma unroll
            for (int mf = 0; mf < 4; ++mf) {
                uint32_t ro = (uint32_t)((wm * 64 + mf * 16 + a_row) * 256) + akoff;
                ldsm_x4(abase + ro, af[mf]);
            }
            #pragma unroll
            for (int nf = 0; nf < 4; ++nf) {
                uint32_t ro = (uint32_t)((wn * 32 + nf * 8 + b_row) * 256) + bkoff;
                ldsm_x2(sm_base + SM_B + ro, bf[nf]);
            }
            #pragma unroll
            for (int mf = 0; mf < 4; ++mf)
                #pragma unroll
                for (int nf = 0; nf < 4; ++nf)
                    mma_f16(acc[mf][nf], af[mf], bf[nf]);
        }

        // ---- Convert + store prefetched tile into the other buffer
        if (pre) {
            const uint32_t obuf = pb ? SM_A0 : SM_A1;
            #pragma unroll
            for (int i = 0; i < 16; ++i) {
                int idx = tid + i * 256;
                int m = idx >> 5, k4 = idx & 31;
                f16_store(smem, obuf, m, k4, regs[i]);
            }
        }

        // ---- Epilogue: bias + fp16 store
        const int node0 = t * 128;
        #pragma unroll
        for (int mf = 0; mf < 4; ++mf) {
            const int node_a = node0 + wm * 64 + mf * 16 + trow;
            const int node_b = node_a + 8;
            #pragma unroll
            for (int nf = 0; nf < 4; ++nf) {
                const int col = wn * 32 + nf * 8 + tcol;
                if (node_a < N_NODES) {
                    __half2 hv = __floats2half2_rn(acc[mf][nf][0] + bias2[nf].x,
                                                   acc[mf][nf][1] + bias2[nf].y);
                    *(__half2*)&g_PQh[(size_t)node_a * NOUT + col] = hv;
                }
                if (node_b < N_NODES) {
                    __half2 hv = __floats2half2_rn(acc[mf][nf][2] + bias2[nf].x,
                                                   acc[mf][nf][3] + bias2[nf].y);
                    *(__half2*)&g_PQh[(size_t)node_b * NOUT + col] = hv;
                }
            }
        }
        __syncthreads();
    }
}

// ---------------------------------------------------------------------------
// Kernel 2: gather-add, 2 edges per thread.
// out[e][c] = PQh[src[e]][c] + PQh[dst[e]][64+c]
// ---------------------------------------------------------------------------
__global__ void __launch_bounds__(256)
gather_kernel(const int* __restrict__ src, const int* __restrict__ dst,
              float* __restrict__ out) {
    int t = blockIdx.x * blockDim.x + threadIdx.x;
    if (t >= (N_EDGES / 2) * 8) return;
    const int ep = t >> 3;
    const int q  = t & 7;
    const int e0 = ep * 2;
    const int e1 = e0 + 1;

    unsigned int s0 = (unsigned int)__ldg(&src[e0]);
    unsigned int d0 = (unsigned int)__ldg(&dst[e0]);
    unsigned int s1 = (unsigned int)__ldg(&src[e1]);
    unsigned int d1 = (unsigned int)__ldg(&dst[e1]);
    if (s0 >= N_NODES) s0 = 0;
    if (d0 >= N_NODES) d0 = 0;
    if (s1 >= N_NODES) s1 = 0;
    if (d1 >= N_NODES) d1 = 0;

    uint4 p0 = *(const uint4*)&g_PQh[(size_t)s0 * NOUT + q * 8];
    uint4 r0 = *(const uint4*)&g_PQh[(size_t)d0 * NOUT + 64 + q * 8];
    uint4 p1 = *(const uint4*)&g_PQh[(size_t)s1 * NOUT + q * 8];
    uint4 r1 = *(const uint4*)&g_PQh[(size_t)d1 * NOUT + 64 + q * 8];

    float o0[8], o1[8];
    {
        const __half2* ph = (const __half2*)&p0;
        const __half2* qh = (const __half2*)&r0;
        #pragma unroll
        for (int i = 0; i < 4; ++i) {
            float2 a = __half22float2(ph[i]);
            float2 c = __half22float2(qh[i]);
            o0[i * 2] = a.x + c.x; o0[i * 2 + 1] = a.y + c.y;
        }
    }
    {
        const __half2* ph = (const __half2*)&p1;
        const __half2* qh = (const __half2*)&r1;
        #pragma unroll
        for (int i = 0; i < 4; ++i) {
            float2 a = __half22float2(ph[i]);
            float2 c = __half22float2(qh[i]);
            o1[i * 2] = a.x + c.x; o1[i * 2 + 1] = a.y + c.y;
        }
    }

    float* op0 = out + (size_t)e0 * 64 + q * 8;
    float* op1 = out + (size_t)e1 * 64 + q * 8;
    __stcs((float4*)op0,     make_float4(o0[0], o0[1], o0[2], o0[3]));
    __stcs((float4*)op0 + 1, make_float4(o0[4], o0[5], o0[6], o0[7]));
    __stcs((float4*)op1,     make_float4(o1[0], o1[1], o1[2], o1[3]));
    __stcs((float4*)op1 + 1, make_float4(o1[4], o1[5], o1[6], o1[7]));
}

// ---------------------------------------------------------------------------
extern "C" void kernel_launch(void* const* d_in, const int* in_sizes, int n_in,
                              void* d_out, int out_size) {
    const float* h   = (const float*)d_in[0];
    const int*   src = (const int*)  d_in[1];
    const int*   dst = (const int*)  d_in[2];
    const float* W   = (const float*)d_in[3];
    const float* b   = (const float*)d_in[4];
    float* out = (float*)d_out;

    cudaFuncSetAttribute(gemm_kernel, cudaFuncAttributeMaxDynamicSharedMemorySize, SM_TOTAL);

    gemm_kernel<<<GRIDX, 256, SM_TOTAL>>>(h, W, b);

    const int gthreads = (N_EDGES / 2) * 8;   // 2.4M
    gather_kernel<<<(gthreads + 255) / 256, 256>>>(src, dst, out);
}